// round 4
// baseline (speedup 1.0000x reference)
#include <cuda_runtime.h>
#include <math.h>

#define B_IMG   64
#define CH      8
#define NPIX    1024
#define NSTATE  (B_IMG*CH*NPIX)     // 524288
#define N_STEPS 24

typedef unsigned long long ull;

__device__ __forceinline__ ull pack2(float lo, float hi) {
  ull r; asm("mov.b64 %0, {%1, %2};" : "=l"(r) : "f"(lo), "f"(hi)); return r;
}
__device__ __forceinline__ float2 unpk(ull v) {
  float2 f; asm("mov.b64 {%0, %1}, %2;" : "=f"(f.x), "=f"(f.y) : "l"(v)); return f;
}
#define FMA2(d,a,b) asm("fma.rn.f32x2 %0, %1, %2, %0;" : "+l"(d) : "l"(a), "l"(b))

__device__ __forceinline__ void cpa16(void* smem_dst, const void* gsrc) {
  unsigned s = (unsigned)__cvta_generic_to_shared(smem_dst);
  asm volatile("cp.async.ca.shared.global [%0], [%1], 16;" :: "r"(s), "l"(gsrc));
}
#define CP_COMMIT() asm volatile("cp.async.commit_group;")
#define CP_WAIT0()  asm volatile("cp.async.wait_group 0;")

// ---------------- device state ----------------
__device__ float g_y[NSTATE];
__device__ float g_y5[NSTATE];
__device__ float g_k[7][NSTATE];
__device__ float g_t, g_dt;
__device__ float g_partial[256];
__device__ int   g_accept;

// packed weights
__device__ ull g_w2p[18432];   // [og4][cc8][ci8][tp9][o2_8]
__device__ ull g_w1s[256];     // [c8][o2_32]
__device__ ull g_w1t[32], g_b1p[32];
__device__ ull g_w3s[256];     // [og4][ci16][o2_4]
__device__ ull g_w3t[4], g_b3p[4];
__device__ ull g_w0s[288];     // [og4][tp9][o2_8]
__device__ ull g_b2p[32];      // [og4][o2_8]

__constant__ float c_toff[7] = {0.f, 0.2f, 0.3f, 0.8f, (float)(8.0/9.0), 1.f, 1.f};
__constant__ float c_coef[7][6] = {
  {0,0,0,0,0,0},
  {0.2f,0,0,0,0,0},
  {(float)(3.0/40.0),(float)(9.0/40.0),0,0,0,0},
  {(float)(44.0/45.0),(float)(-56.0/15.0),(float)(32.0/9.0),0,0,0},
  {(float)(19372.0/6561.0),(float)(-25360.0/2187.0),(float)(64448.0/6561.0),(float)(-212.0/729.0),0,0},
  {(float)(9017.0/3168.0),(float)(-355.0/33.0),(float)(46732.0/5247.0),(float)(49.0/176.0),(float)(-5103.0/18656.0),0},
  {(float)(35.0/384.0),0.f,(float)(500.0/1113.0),(float)(125.0/192.0),(float)(-2187.0/6784.0),(float)(11.0/84.0)}
};
#define E1f ((float)(71.0/57600.0))
#define E3f ((float)(-71.0/16695.0))
#define E4f ((float)(71.0/1920.0))
#define E5f ((float)(-17253.0/339200.0))
#define E6f ((float)(22.0/525.0))
#define E7f ((float)(-1.0/40.0))

// ---------------- init ----------------
__global__ void init_kernel(const float* __restrict__ x) {
  int i = blockIdx.x * 256 + threadIdx.x;
  if (i == 0) { g_t = 0.f; g_dt = 0.1f; g_accept = 0; }
  if (i < NSTATE) {
    int c = i & 7, p = (i >> 3) & 1023, b = i >> 13;
    g_y[i] = (c < 3) ? x[b*3*NPIX + c*NPIX + p] : 0.f;
  }
}

// ---------------- weight prep ----------------
__global__ void prep_kernel(const float* __restrict__ w1, const float* __restrict__ b1,
                            const float* __restrict__ w2, const float* __restrict__ b2,
                            const float* __restrict__ w3, const float* __restrict__ b3) {
  int i = blockIdx.x * 256 + threadIdx.x;
  if (i < 18432) {
    int o2 = i & 7, tp = (i >> 3) % 9, rem = i / 72;
    int ci = rem & 7, cc = (rem >> 3) & 7, og = rem >> 6;
    int r = (og*16 + 2*o2)*585 + (cc*8 + ci + 1)*9 + tp;
    g_w2p[i] = pack2(w2[r], w2[r + 585]);
  }
  if (i < 256) {
    int c = i >> 5, o2 = i & 31;
    g_w1s[i] = pack2(w1[(2*o2)*9 + 1 + c], w1[(2*o2+1)*9 + 1 + c]);
  }
  if (i < 32) {
    g_w1t[i] = pack2(w1[(2*i)*9], w1[(2*i+1)*9]);
    g_b1p[i] = pack2(b1[2*i], b1[2*i+1]);
  }
  if (i < 256) {
    int og = i >> 6, ci = (i >> 2) & 15, o2 = i & 3;
    g_w3s[i] = pack2(w3[(2*o2)*65 + 1 + og*16 + ci], w3[(2*o2+1)*65 + 1 + og*16 + ci]);
  }
  if (i < 4) {
    g_w3t[i] = pack2(w3[(2*i)*65], w3[(2*i+1)*65]);
    g_b3p[i] = pack2(b3[2*i], b3[2*i+1]);
  }
  if (i < 288) {
    int og = i / 72, tp = (i >> 3) % 9, o2 = i & 7;
    g_w0s[i] = pack2(w2[(og*16 + 2*o2)*585 + tp], w2[(og*16 + 2*o2 + 1)*585 + tp]);
  }
  if (i < 32) {
    int og = i >> 3, o2 = i & 7;
    g_b2p[i] = pack2(b2[og*16 + 2*o2], b2[og*16 + 2*o2 + 1]);
  }
}

// ---------------- fused stage kernel ----------------
// 256 threads, 1 pixel/thread, tile = 8 rows x 32 cols.
#define SM_H1   0           // float h1s[64][340]   87040 B
#define SM_WB   87040       // ull wb[2][576]        9216 B
#define SM_W1   96256       // ull w1s[256]          2048 B
#define SM_B1   98304       // ull bias1[32]          256 B
#define SM_W3   98560       // ull w3s[256]          2048 B
#define SM_W0   100608      // ull w0s[288]          2304 B
#define SM_B2   102912      // ull b2s[32]            256 B
#define SM_RED  103168      // float red[256]        1024 B
#define SMEM_BYTES 104192

__global__ __launch_bounds__(256, 2) void fused_kernel(int stage) {
  extern __shared__ char smraw[];
  float* h1s  = (float*)(smraw + SM_H1);
  ull*   wb   = (ull*)  (smraw + SM_WB);
  ull*   w1s  = (ull*)  (smraw + SM_W1);
  ull*   bias1= (ull*)  (smraw + SM_B1);
  ull*   w3s  = (ull*)  (smraw + SM_W3);
  ull*   w0s  = (ull*)  (smraw + SM_W0);
  ull*   b2s  = (ull*)  (smraw + SM_B2);
  float* red  = (float*)(smraw + SM_RED);

  int tid = threadIdx.x;
  int b = blockIdx.x, tile = blockIdx.y;
  int r0 = tile * 8;

  float tcur = g_t;
  float dtc  = fminf(g_dt, 1.f - tcur);
  float teval = tcur + c_toff[stage] * dtc;
  ull tev2 = pack2(teval, teval);

  for (int i = tid; i < 256; i += 256) w1s[i] = g_w1s[i];
  for (int i = tid; i < 256; i += 256) w3s[i] = g_w3s[i];
  for (int i = tid; i < 288; i += 256) w0s[i] = g_w0s[i];
  if (tid < 32) { ull bb = g_b1p[tid]; FMA2(bb, tev2, g_w1t[tid]); bias1[tid] = bb; }
  if (tid < 32) b2s[tid] = g_b2p[tid];

  for (int i = tid; i < 288; i += 256) cpa16(wb + i*2, g_w2p + i*2);
  CP_COMMIT();
  __syncthreads();

  // ---- conv1: fill 10x34 haloed h1 tile ----
  for (int p = tid; p < 340; p += 256) {
    int prow = p / 34, pcol = p - prow*34;
    int gr = r0 - 1 + prow, gc = pcol - 1;
    bool valid = (gr >= 0) && (gr < 32) && (gc >= 0) && (gc < 32);
    if (!valid) {
      #pragma unroll 8
      for (int o = 0; o < 64; o++) h1s[o*340 + p] = 0.f;
    } else {
      int idx = b*1024 + gr*32 + gc;
      const float4* yp = (const float4*)g_y;
      float4 ya = yp[idx*2], yb = yp[idx*2+1];
      float yt[8] = {ya.x, ya.y, ya.z, ya.w, yb.x, yb.y, yb.z, yb.w};
      for (int j = 0; j < stage; j++) {
        float cf = c_coef[stage][j];
        if (cf != 0.f) {
          float a = dtc * cf;
          const float4* kj = (const float4*)g_k[j];
          float4 k0 = kj[idx*2], k1 = kj[idx*2+1];
          yt[0]+=a*k0.x; yt[1]+=a*k0.y; yt[2]+=a*k0.z; yt[3]+=a*k0.w;
          yt[4]+=a*k1.x; yt[5]+=a*k1.y; yt[6]+=a*k1.z; yt[7]+=a*k1.w;
        }
      }
      ull yy[8];
      #pragma unroll
      for (int c8 = 0; c8 < 8; c8++) yy[c8] = pack2(yt[c8], yt[c8]);
      #pragma unroll
      for (int o4 = 0; o4 < 16; o4++) {
        ull a0 = bias1[2*o4], a1 = bias1[2*o4+1];
        #pragma unroll
        for (int c8 = 0; c8 < 8; c8++) {
          FMA2(a0, yy[c8], w1s[c8*32 + 2*o4]);
          FMA2(a1, yy[c8], w1s[c8*32 + 2*o4 + 1]);
        }
        float2 f0 = unpk(a0), f1 = unpk(a1);
        h1s[(4*o4+0)*340 + p] = fmaxf(f0.x, 0.f);
        h1s[(4*o4+1)*340 + p] = fmaxf(f0.y, 0.f);
        h1s[(4*o4+2)*340 + p] = fmaxf(f1.x, 0.f);
        h1s[(4*o4+3)*340 + p] = fmaxf(f1.y, 0.f);
      }
    }
  }
  __syncthreads();

  // ---- conv2 + fused conv3, 1 px/thread ----
  int c  = tid & 31;
  int rb = tid >> 5;              // row within tile (0..7)

  ull kacc[4];
  #pragma unroll
  for (int o2 = 0; o2 < 4; o2++) {
    ull kk = g_b3p[o2]; FMA2(kk, tev2, g_w3t[o2]);
    kacc[o2] = kk;
  }

  int cur = 0;
  #pragma unroll 1
  for (int og = 0; og < 4; og++) {
    ull acc[8];
    #pragma unroll
    for (int o2 = 0; o2 < 8; o2++) acc[o2] = 0ULL;

    #pragma unroll 1
    for (int cc = 0; cc < 8; cc++) {
      CP_WAIT0();
      __syncthreads();
      int nchunk = og*8 + cc + 1;
      if (nchunk < 32) {
        ull* dst = wb + (cur^1)*576;
        const ull* src = g_w2p + nchunk*576;
        for (int i = tid; i < 288; i += 256) cpa16(dst + i*2, src + i*2);
        CP_COMMIT();
      }
      const ull* wc = wb + cur*576;
      #pragma unroll 1
      for (int ci = 0; ci < 8; ci++) {
        const float* pl = h1s + (cc*8 + ci)*340;
        ull v[9];
        #pragma unroll
        for (int kh = 0; kh < 3; kh++)
          #pragma unroll
          for (int kw = 0; kw < 3; kw++) {
            float a = pl[(rb+kh)*34 + c + kw];
            v[kh*3+kw] = pack2(a, a);
          }
        const ulonglong2* wr = (const ulonglong2*)(wc + ci*72);
        #pragma unroll
        for (int o2p = 0; o2p < 4; o2p++) {
          #pragma unroll
          for (int tp = 0; tp < 9; tp++) {
            ulonglong2 wp = wr[tp*4 + o2p];
            FMA2(acc[2*o2p],   v[tp], wp.x);
            FMA2(acc[2*o2p+1], v[tp], wp.y);
          }
        }
      }
      cur ^= 1;
    }

    // ---- epilogue: t-channel + bias + relu -> conv3 partial ----
    {
      int gr = r0 + rb, gc = c;
      #pragma unroll
      for (int tp = 0; tp < 9; tp++) {
        int kh = tp / 3, kw = tp - kh*3;
        bool ok = !((kh==0 && gr==0) || (kh==2 && gr==31) ||
                    (kw==0 && gc==0) || (kw==2 && gc==31));
        if (ok) {
          #pragma unroll
          for (int o2 = 0; o2 < 8; o2++)
            FMA2(acc[o2], tev2, w0s[og*72 + tp*8 + o2]);
        }
      }
      float h[16];
      #pragma unroll
      for (int q = 0; q < 8; q++) {
        float2 bb = unpk(b2s[og*8 + q]);
        float2 f  = unpk(acc[q]);
        h[2*q]   = fmaxf(f.x + bb.x, 0.f);
        h[2*q+1] = fmaxf(f.y + bb.y, 0.f);
      }
      #pragma unroll
      for (int ci = 0; ci < 16; ci++) {
        ull hh = pack2(h[ci], h[ci]);
        const ull* w3r = w3s + og*64 + ci*4;
        FMA2(kacc[0], hh, w3r[0]);
        FMA2(kacc[1], hh, w3r[1]);
        FMA2(kacc[2], hh, w3r[2]);
        FMA2(kacc[3], hh, w3r[3]);
      }
    }
  }

  // ---- write k; stage 6: y5 + err partials ----
  float local = 0.f;
  float* kd = g_k[stage];
  {
    int gr = r0 + rb;
    int idx = b*1024 + gr*32 + c;
    float2 q0 = unpk(kacc[0]), q1 = unpk(kacc[1]);
    float2 q2 = unpk(kacc[2]), q3 = unpk(kacc[3]);
    float kv[8] = {q0.x, q0.y, q1.x, q1.y, q2.x, q2.y, q3.x, q3.y};
    float4* kp = (float4*)kd;
    kp[idx*2]   = make_float4(kv[0], kv[1], kv[2], kv[3]);
    kp[idx*2+1] = make_float4(kv[4], kv[5], kv[6], kv[7]);

    if (stage == 6) {
      const float4* yp = (const float4*)g_y;
      float4 ya = yp[idx*2], yb = yp[idx*2+1];
      float yv[8] = {ya.x, ya.y, ya.z, ya.w, yb.x, yb.y, yb.z, yb.w};
      float yt[8], e[8];
      #pragma unroll
      for (int c8 = 0; c8 < 8; c8++) { yt[c8] = yv[c8]; e[c8] = E7f * kv[c8]; }
      const int   jidx[5] = {0, 2, 3, 4, 5};
      const float bcf[5]  = {(float)(35.0/384.0), (float)(500.0/1113.0),
                             (float)(125.0/192.0), (float)(-2187.0/6784.0),
                             (float)(11.0/84.0)};
      const float ecf[5]  = {E1f, E3f, E4f, E5f, E6f};
      #pragma unroll
      for (int j = 0; j < 5; j++) {
        const float4* kj = (const float4*)g_k[jidx[j]];
        float4 k0 = kj[idx*2], k1 = kj[idx*2+1];
        float kk[8] = {k0.x, k0.y, k0.z, k0.w, k1.x, k1.y, k1.z, k1.w};
        float a = dtc * bcf[j];
        #pragma unroll
        for (int c8 = 0; c8 < 8; c8++) { yt[c8] += a * kk[c8]; e[c8] += ecf[j] * kk[c8]; }
      }
      float4* y5p = (float4*)g_y5;
      y5p[idx*2]   = make_float4(yt[0], yt[1], yt[2], yt[3]);
      y5p[idx*2+1] = make_float4(yt[4], yt[5], yt[6], yt[7]);
      #pragma unroll
      for (int c8 = 0; c8 < 8; c8++) {
        float err = dtc * e[c8];
        float tol = 1e-3f + 1e-3f * fmaxf(fabsf(yv[c8]), fabsf(yt[c8]));
        float r = err / tol;
        local += r * r;
      }
    }
  }

  if (stage == 6) {
    red[tid] = local; __syncthreads();
    for (int s = 128; s > 0; s >>= 1) { if (tid < s) red[tid] += red[tid+s]; __syncthreads(); }
    if (tid == 0) g_partial[tile*64 + b] = red[0];
  }
}

// ---------------- step controller ----------------
__global__ void update_kernel() {
  __shared__ float red[256];
  int tid = threadIdx.x;
  red[tid] = g_partial[tid];
  __syncthreads();
  for (int s = 128; s > 0; s >>= 1) { if (tid < s) red[tid] += red[tid+s]; __syncthreads(); }
  if (tid == 0) {
    float err_norm = sqrtf(red[0] * (1.f / (float)NSTATE));
    float tcur = g_t, dt = g_dt;
    float dtc  = fminf(dt, 1.f - tcur);
    bool done = tcur >= 1.f - 1e-7f;
    bool adv  = (err_norm <= 1.f) && (!done);
    g_accept = adv ? 1 : 0;
    g_t = adv ? (tcur + dtc) : tcur;
    float safe = fmaxf(err_norm, 1e-10f);
    float factor = 0.9f * powf(safe, -0.2f);
    factor = fminf(fmaxf(factor, 0.2f), 10.f);
    g_dt = done ? dt : dtc * factor;
  }
}

__global__ void commit_kernel() {
  if (g_accept == 0) return;
  int i = blockIdx.x * 256 + threadIdx.x;
  g_y[i] = g_y5[i];
}

// ---------------- final linear head ----------------
__global__ __launch_bounds__(256) void head_kernel(const float* __restrict__ wl,
                                                   const float* __restrict__ bl,
                                                   float* __restrict__ out) {
  __shared__ float ys[8192];
  __shared__ float red[256];
  int b = blockIdx.x, tid = threadIdx.x;
  const float* yb = g_y + (size_t)b * 8192;
  for (int i = tid; i < 8192; i += 256) {
    int px = i >> 3, c = i & 7;
    ys[c*1024 + px] = yb[i];
  }
  __syncthreads();
  for (int o = 0; o < 10; o++) {
    float s = 0.f;
    const float* wo = wl + (size_t)o * 8192;
    for (int i = tid; i < 8192; i += 256) s += wo[i] * ys[i];
    red[tid] = s; __syncthreads();
    for (int st = 128; st > 0; st >>= 1) { if (tid < st) red[tid] += red[tid+st]; __syncthreads(); }
    if (tid == 0) out[b*10 + o] = red[0] + bl[o];
    __syncthreads();
  }
}

// ---------------- launcher ----------------
extern "C" void kernel_launch(void* const* d_in, const int* in_sizes, int n_in,
                              void* d_out, int out_size) {
  const float* x  = (const float*)d_in[0];
  const float* w1 = (const float*)d_in[1];
  const float* b1 = (const float*)d_in[2];
  const float* w2 = (const float*)d_in[3];
  const float* b2 = (const float*)d_in[4];
  const float* w3 = (const float*)d_in[5];
  const float* b3 = (const float*)d_in[6];
  const float* wl = (const float*)d_in[7];
  const float* bl = (const float*)d_in[8];
  float* out = (float*)d_out;

  cudaFuncSetAttribute(fused_kernel, cudaFuncAttributeMaxDynamicSharedMemorySize, SMEM_BYTES);

  init_kernel<<<NSTATE/256, 256>>>(x);
  prep_kernel<<<72, 256>>>(w1, b1, w2, b2, w3, b3);
  for (int step = 0; step < N_STEPS; step++) {
    commit_kernel<<<NSTATE/256, 256>>>();
    for (int s = 0; s < 7; s++)
      fused_kernel<<<dim3(B_IMG, 4), 256, SMEM_BYTES>>>(s);
    update_kernel<<<1, 256>>>();
  }
  commit_kernel<<<NSTATE/256, 256>>>();
  head_kernel<<<B_IMG, 256>>>(wl, bl, out);
}

// round 6
// speedup vs baseline: 1.4605x; 1.4605x over previous
#include <cuda_runtime.h>
#include <math.h>

#define B_IMG   64
#define CH      8
#define NPIX    1024
#define NSTATE  (B_IMG*CH*NPIX)     // 524288
#define N_STEPS 24

typedef unsigned long long ull;

__device__ __forceinline__ ull pack2(float lo, float hi) {
  ull r; asm("mov.b64 %0, {%1, %2};" : "=l"(r) : "f"(lo), "f"(hi)); return r;
}
__device__ __forceinline__ float2 unpk(ull v) {
  float2 f; asm("mov.b64 {%0, %1}, %2;" : "=f"(f.x), "=f"(f.y) : "l"(v)); return f;
}
#define FMA2(d,a,b) asm("fma.rn.f32x2 %0, %1, %2, %0;" : "+l"(d) : "l"(a), "l"(b))

__device__ __forceinline__ void cpa16(void* smem_dst, const void* gsrc) {
  unsigned s = (unsigned)__cvta_generic_to_shared(smem_dst);
  asm volatile("cp.async.ca.shared.global [%0], [%1], 16;" :: "r"(s), "l"(gsrc));
}
#define CP_COMMIT() asm volatile("cp.async.commit_group;")
#define CP_WAIT0()  asm volatile("cp.async.wait_group 0;")

// ---------------- device state ----------------
__device__ float g_y[NSTATE];
__device__ float g_y5[NSTATE];
__device__ float g_kp[2][7][NSTATE];   // conv3 partial sums (och halves)
__device__ float g_t, g_dt;
__device__ float g_partial[2048];
__device__ int   g_accept;

// packed weights
__device__ ull g_w2p[18432];   // [og4][cc8][ci8][tp9][o2_8]
__device__ ull g_w1s[256];     // [c8][o2_32]
__device__ ull g_w1t[32], g_b1p[32];
__device__ ull g_w3s[256];     // [og4][ci16][o2_4]
__device__ ull g_w3t[4], g_b3p[4];
__device__ ull g_w0s[288];     // [og4][tp9][o2_8]
__device__ ull g_b2p[32];      // [og4][o2_8]

__constant__ float c_toff[7] = {0.f, 0.2f, 0.3f, 0.8f, (float)(8.0/9.0), 1.f, 1.f};
__constant__ float c_coef[7][6] = {
  {0,0,0,0,0,0},
  {0.2f,0,0,0,0,0},
  {(float)(3.0/40.0),(float)(9.0/40.0),0,0,0,0},
  {(float)(44.0/45.0),(float)(-56.0/15.0),(float)(32.0/9.0),0,0,0},
  {(float)(19372.0/6561.0),(float)(-25360.0/2187.0),(float)(64448.0/6561.0),(float)(-212.0/729.0),0,0},
  {(float)(9017.0/3168.0),(float)(-355.0/33.0),(float)(46732.0/5247.0),(float)(49.0/176.0),(float)(-5103.0/18656.0),0},
  {(float)(35.0/384.0),0.f,(float)(500.0/1113.0),(float)(125.0/192.0),(float)(-2187.0/6784.0),(float)(11.0/84.0)}
};
#define B1f ((float)(35.0/384.0))
#define B3f ((float)(500.0/1113.0))
#define B4f ((float)(125.0/192.0))
#define B5f ((float)(-2187.0/6784.0))
#define B6f ((float)(11.0/84.0))
#define E1f ((float)(71.0/57600.0))
#define E3f ((float)(-71.0/16695.0))
#define E4f ((float)(71.0/1920.0))
#define E5f ((float)(-17253.0/339200.0))
#define E6f ((float)(22.0/525.0))
#define E7f ((float)(-1.0/40.0))

// ---------------- init ----------------
__global__ void init_kernel(const float* __restrict__ x) {
  int i = blockIdx.x * 256 + threadIdx.x;
  if (i == 0) { g_t = 0.f; g_dt = 0.1f; g_accept = 0; }
  if (i < NSTATE) {
    int c = i & 7, p = (i >> 3) & 1023, b = i >> 13;
    g_y[i] = (c < 3) ? x[b*3*NPIX + c*NPIX + p] : 0.f;
  }
}

// ---------------- weight prep ----------------
__global__ void prep_kernel(const float* __restrict__ w1, const float* __restrict__ b1,
                            const float* __restrict__ w2, const float* __restrict__ b2,
                            const float* __restrict__ w3, const float* __restrict__ b3) {
  int i = blockIdx.x * 256 + threadIdx.x;
  if (i < 18432) {
    int o2 = i & 7, tp = (i >> 3) % 9, rem = i / 72;
    int ci = rem & 7, cc = (rem >> 3) & 7, og = rem >> 6;
    int r = (og*16 + 2*o2)*585 + (cc*8 + ci + 1)*9 + tp;
    g_w2p[i] = pack2(w2[r], w2[r + 585]);
  }
  if (i < 256) {
    int c = i >> 5, o2 = i & 31;
    g_w1s[i] = pack2(w1[(2*o2)*9 + 1 + c], w1[(2*o2+1)*9 + 1 + c]);
  }
  if (i < 32) {
    g_w1t[i] = pack2(w1[(2*i)*9], w1[(2*i+1)*9]);
    g_b1p[i] = pack2(b1[2*i], b1[2*i+1]);
  }
  if (i < 256) {
    int og = i >> 6, ci = (i >> 2) & 15, o2 = i & 3;
    g_w3s[i] = pack2(w3[(2*o2)*65 + 1 + og*16 + ci], w3[(2*o2+1)*65 + 1 + og*16 + ci]);
  }
  if (i < 4) {
    g_w3t[i] = pack2(w3[(2*i)*65], w3[(2*i+1)*65]);
    g_b3p[i] = pack2(b3[2*i], b3[2*i+1]);
  }
  if (i < 288) {
    int og = i / 72, tp = (i >> 3) % 9, o2 = i & 7;
    g_w0s[i] = pack2(w2[(og*16 + 2*o2)*585 + tp], w2[(og*16 + 2*o2 + 1)*585 + tp]);
  }
  if (i < 32) {
    int og = i >> 3, o2 = i & 7;
    g_b2p[i] = pack2(b2[og*16 + 2*o2], b2[og*16 + 2*o2 + 1]);
  }
}

// ---------------- fused stage kernel ----------------
// grid (64 img, 4 tiles, 2 och-halves); block 128 threads; 2 adjacent-row px/thread.
#define SM_YTS  0        // float yts[340][8]        10880 B
#define SM_H1   10880    // float h1s[8][340]        10880 B
#define SM_WB   21760    // ull wb[2][1152]          18432 B
#define SM_W1   40192    // ull w1s[256]              2048 B
#define SM_B1   42240    // ull bias1[32]              256 B
#define SM_W3   42496    // ull w3s[256]              2048 B
#define SM_W0   44544    // ull w0s[288]              2304 B
#define SM_B2   46848    // ull b2s[32]                256 B
#define SMEM_BYTES 47104

__global__ __launch_bounds__(128, 3) void fused_kernel(int stage) {
  extern __shared__ char smraw[];
  float* yts  = (float*)(smraw + SM_YTS);
  float* h1s  = (float*)(smraw + SM_H1);
  ull*   wb   = (ull*)  (smraw + SM_WB);
  ull*   w1s  = (ull*)  (smraw + SM_W1);
  ull*   bias1= (ull*)  (smraw + SM_B1);
  ull*   w3s  = (ull*)  (smraw + SM_W3);
  ull*   w0s  = (ull*)  (smraw + SM_W0);
  ull*   b2s  = (ull*)  (smraw + SM_B2);

  int tid  = threadIdx.x;
  int b    = blockIdx.x;
  int tile = blockIdx.y;
  int half = blockIdx.z;
  int r0   = tile * 8;

  float tcur = g_t;
  float dtc  = fminf(g_dt, 1.f - tcur);
  float teval = tcur + c_toff[stage] * dtc;
  ull tev2 = pack2(teval, teval);

  for (int i = tid; i < 256; i += 128) w1s[i] = g_w1s[i];
  for (int i = tid; i < 256; i += 128) w3s[i] = g_w3s[i];
  for (int i = tid; i < 288; i += 128) w0s[i] = g_w0s[i];
  if (tid < 32) { ull bb = g_b1p[tid]; FMA2(bb, tev2, g_w1t[tid]); bias1[tid] = bb; }
  if (tid < 32) b2s[tid] = g_b2p[tid];

  // prefetch conv2 weight chunk cc=0 for this half (two og slabs) into buffer 0
  {
    const ull* s0 = g_w2p + (half*2)*4608;
    const ull* s1 = g_w2p + (half*2+1)*4608;
    for (int i = tid; i < 288; i += 128) {
      cpa16(wb + i*2, s0 + i*2);
      cpa16(wb + 576 + i*2, s1 + i*2);
    }
    CP_COMMIT();
  }

  // ---- phase A: stage-combined state into yts (haloed 10x34) ----
  for (int p = tid; p < 340; p += 128) {
    int prow = p / 34, pcol = p - prow*34;
    int gr = r0 - 1 + prow, gc = pcol - 1;
    float4 o0 = make_float4(0.f,0.f,0.f,0.f), o1 = o0;
    if (gr >= 0 && gr < 32 && gc >= 0 && gc < 32) {
      int idx = b*1024 + gr*32 + gc;
      const float4* yp = (const float4*)g_y;
      o0 = yp[idx*2]; o1 = yp[idx*2+1];
      for (int j = 0; j < stage; j++) {
        float cf = c_coef[stage][j];
        if (cf != 0.f) {
          float a = dtc * cf;
          const float4* k0p = (const float4*)g_kp[0][j];
          const float4* k1p = (const float4*)g_kp[1][j];
          float4 p0 = k0p[idx*2], p1 = k0p[idx*2+1];
          float4 q0 = k1p[idx*2], q1 = k1p[idx*2+1];
          o0.x += a*(p0.x+q0.x); o0.y += a*(p0.y+q0.y);
          o0.z += a*(p0.z+q0.z); o0.w += a*(p0.w+q0.w);
          o1.x += a*(p1.x+q1.x); o1.y += a*(p1.y+q1.y);
          o1.z += a*(p1.z+q1.z); o1.w += a*(p1.w+q1.w);
        }
      }
    }
    float4* dst = (float4*)(yts + p*8);
    dst[0] = o0; dst[1] = o1;
  }

  // ---- main loop over 8 cc-chunks ----
  int c  = tid & 31;
  int rp = tid >> 5;              // row pair: rows 2rp, 2rp+1 (tile-local)

  ull acc0[16], acc1[16];         // [slab*8 + o2], slab = og within half
  #pragma unroll
  for (int o = 0; o < 16; o++) { acc0[o] = 0ULL; acc1[o] = 0ULL; }

  int cur = 0;
  #pragma unroll 1
  for (int cc = 0; cc < 8; cc++) {
    __syncthreads();   // h1s free (prev conv2 done), yts ready (cc=0)

    // conv1: produce h1 channels cc*8..cc*8+7 for all 340 haloed px
    #pragma unroll 1
    for (int p = tid; p < 340; p += 128) {
      int prow = p / 34, pcol = p - prow*34;
      int gr = r0 - 1 + prow, gc = pcol - 1;
      float o[8];
      if (gr >= 0 && gr < 32 && gc >= 0 && gc < 32) {
        const float4* yv = (const float4*)(yts + p*8);
        float4 a4 = yv[0], b4 = yv[1];
        float yf[8] = {a4.x, a4.y, a4.z, a4.w, b4.x, b4.y, b4.z, b4.w};
        ull yy[8];
        #pragma unroll
        for (int c8 = 0; c8 < 8; c8++) yy[c8] = pack2(yf[c8], yf[c8]);
        #pragma unroll
        for (int q = 0; q < 4; q++) {
          ull aq = bias1[cc*4 + q];
          #pragma unroll
          for (int c8 = 0; c8 < 8; c8++) FMA2(aq, yy[c8], w1s[c8*32 + cc*4 + q]);
          float2 f = unpk(aq);
          o[2*q]   = fmaxf(f.x, 0.f);
          o[2*q+1] = fmaxf(f.y, 0.f);
        }
      } else {
        #pragma unroll
        for (int q = 0; q < 8; q++) o[q] = 0.f;
      }
      #pragma unroll
      for (int ci = 0; ci < 8; ci++) h1s[ci*340 + p] = o[ci];
    }

    CP_WAIT0();
    __syncthreads();   // h1s written, wb[cur] ready

    if (cc < 7) {
      const ull* s0 = g_w2p + (half*2)*4608 + (cc+1)*576;
      const ull* s1 = g_w2p + (half*2+1)*4608 + (cc+1)*576;
      ull* d = wb + (cur^1)*1152;
      for (int i = tid; i < 288; i += 128) {
        cpa16(d + i*2, s0 + i*2);
        cpa16(d + 576 + i*2, s1 + i*2);
      }
      CP_COMMIT();
    }

    const ull* wc = wb + cur*1152;
    #pragma unroll 1
    for (int ci = 0; ci < 8; ci++) {
      const float* pl = h1s + ci*340;
      // shared 4x3 window: halo rows 2rp..2rp+3, cols c..c+2
      ull v[4][3];
      #pragma unroll
      for (int rw = 0; rw < 4; rw++)
        #pragma unroll
        for (int cw = 0; cw < 3; cw++) {
          float a = pl[(2*rp + rw)*34 + c + cw];
          v[rw][cw] = pack2(a, a);
        }
      #pragma unroll
      for (int s = 0; s < 2; s++) {
        const ulonglong2* wr = (const ulonglong2*)(wc + s*576 + ci*72);
        #pragma unroll
        for (int kh = 0; kh < 3; kh++)
          #pragma unroll
          for (int kw = 0; kw < 3; kw++) {
            int tp = kh*3 + kw;
            #pragma unroll
            for (int q = 0; q < 4; q++) {
              ulonglong2 wp = wr[tp*4 + q];
              FMA2(acc0[s*8+2*q],   v[kh][kw],   wp.x);
              FMA2(acc0[s*8+2*q+1], v[kh][kw],   wp.y);
              FMA2(acc1[s*8+2*q],   v[kh+1][kw], wp.x);
              FMA2(acc1[s*8+2*q+1], v[kh+1][kw], wp.y);
            }
          }
      }
    }
    cur ^= 1;
  }

  // ---- epilogue: t-channel + bias + relu -> conv3 partial ----
  ull kacc0[4], kacc1[4];
  #pragma unroll
  for (int o2 = 0; o2 < 4; o2++) {
    ull kk = 0ULL;
    if (half == 0) { kk = g_b3p[o2]; FMA2(kk, tev2, g_w3t[o2]); }
    kacc0[o2] = kk; kacc1[o2] = kk;
  }

  #pragma unroll
  for (int s = 0; s < 2; s++) {
    int og = half*2 + s;
    #pragma unroll
    for (int px = 0; px < 2; px++) {
      ull* acc = px ? acc1 : acc0;
      ull* kacc = px ? kacc1 : kacc0;
      int gr = r0 + 2*rp + px, gc = c;
      #pragma unroll
      for (int tp = 0; tp < 9; tp++) {
        int kh = tp / 3, kw = tp - kh*3;
        bool ok = !((kh==0 && gr==0) || (kh==2 && gr==31) ||
                    (kw==0 && gc==0) || (kw==2 && gc==31));
        if (ok) {
          #pragma unroll
          for (int o2 = 0; o2 < 8; o2++)
            FMA2(acc[s*8+o2], tev2, w0s[og*72 + tp*8 + o2]);
        }
      }
      float h[16];
      #pragma unroll
      for (int q = 0; q < 8; q++) {
        float2 bb = unpk(b2s[og*8 + q]);
        float2 f  = unpk(acc[s*8+q]);
        h[2*q]   = fmaxf(f.x + bb.x, 0.f);
        h[2*q+1] = fmaxf(f.y + bb.y, 0.f);
      }
      #pragma unroll
      for (int ci = 0; ci < 16; ci++) {
        ull hh = pack2(h[ci], h[ci]);
        const ull* w3r = w3s + og*64 + ci*4;
        FMA2(kacc[0], hh, w3r[0]);
        FMA2(kacc[1], hh, w3r[1]);
        FMA2(kacc[2], hh, w3r[2]);
        FMA2(kacc[3], hh, w3r[3]);
      }
    }
  }

  // ---- write k partials ----
  float4* kp = (float4*)g_kp[half][stage];
  #pragma unroll
  for (int px = 0; px < 2; px++) {
    ull* kacc = px ? kacc1 : kacc0;
    int gr = r0 + 2*rp + px;
    int idx = b*1024 + gr*32 + c;
    float2 q0 = unpk(kacc[0]), q1 = unpk(kacc[1]);
    float2 q2 = unpk(kacc[2]), q3 = unpk(kacc[3]);
    kp[idx*2]   = make_float4(q0.x, q0.y, q1.x, q1.y);
    kp[idx*2+1] = make_float4(q2.x, q2.y, q3.x, q3.y);
  }
}

// ---------------- y5 + error partials (per step, after stage 6) ----------------
__global__ __launch_bounds__(256) void err_kernel() {
  __shared__ float red[256];
  int tid = threadIdx.x;
  int e = blockIdx.x * 256 + tid;
  float dtc = fminf(g_dt, 1.f - g_t);
  float k0 = g_kp[0][0][e] + g_kp[1][0][e];
  float k2 = g_kp[0][2][e] + g_kp[1][2][e];
  float k3 = g_kp[0][3][e] + g_kp[1][3][e];
  float k4 = g_kp[0][4][e] + g_kp[1][4][e];
  float k5 = g_kp[0][5][e] + g_kp[1][5][e];
  float k6 = g_kp[0][6][e] + g_kp[1][6][e];
  float yv = g_y[e];
  float y5 = yv + dtc*(B1f*k0 + B3f*k2 + B4f*k3 + B5f*k4 + B6f*k5);
  g_y5[e] = y5;
  float err = dtc*(E1f*k0 + E3f*k2 + E4f*k3 + E5f*k4 + E6f*k5 + E7f*k6);
  float tol = 1e-3f + 1e-3f * fmaxf(fabsf(yv), fabsf(y5));
  float r = err / tol;
  red[tid] = r * r;
  __syncthreads();
  for (int s = 128; s > 0; s >>= 1) { if (tid < s) red[tid] += red[tid+s]; __syncthreads(); }
  if (tid == 0) g_partial[blockIdx.x] = red[0];
}

// ---------------- step controller ----------------
__global__ void update_kernel() {
  __shared__ float red[256];
  int tid = threadIdx.x;
  float s0 = 0.f;
  for (int i = tid; i < 2048; i += 256) s0 += g_partial[i];
  red[tid] = s0;
  __syncthreads();
  for (int s = 128; s > 0; s >>= 1) { if (tid < s) red[tid] += red[tid+s]; __syncthreads(); }
  if (tid == 0) {
    float err_norm = sqrtf(red[0] * (1.f / (float)NSTATE));
    float tcur = g_t, dt = g_dt;
    float dtc  = fminf(dt, 1.f - tcur);
    bool done = tcur >= 1.f - 1e-7f;
    bool adv  = (err_norm <= 1.f) && (!done);
    g_accept = adv ? 1 : 0;
    g_t = adv ? (tcur + dtc) : tcur;
    float safe = fmaxf(err_norm, 1e-10f);
    float factor = 0.9f * powf(safe, -0.2f);
    factor = fminf(fmaxf(factor, 0.2f), 10.f);
    g_dt = done ? dt : dtc * factor;
  }
}

__global__ void commit_kernel() {
  if (g_accept == 0) return;
  int i = blockIdx.x * 256 + threadIdx.x;
  g_y[i] = g_y5[i];
}

// ---------------- final linear head ----------------
__global__ __launch_bounds__(256) void head_kernel(const float* __restrict__ wl,
                                                   const float* __restrict__ bl,
                                                   float* __restrict__ out) {
  __shared__ float ys[8192];
  __shared__ float red[256];
  int b = blockIdx.x, tid = threadIdx.x;
  const float* yb = g_y + (size_t)b * 8192;
  for (int i = tid; i < 8192; i += 256) {
    int px = i >> 3, c = i & 7;
    ys[c*1024 + px] = yb[i];
  }
  __syncthreads();
  for (int o = 0; o < 10; o++) {
    float s = 0.f;
    const float* wo = wl + (size_t)o * 8192;
    for (int i = tid; i < 8192; i += 256) s += wo[i] * ys[i];
    red[tid] = s; __syncthreads();
    for (int st = 128; st > 0; st >>= 1) { if (tid < st) red[tid] += red[tid+st]; __syncthreads(); }
    if (tid == 0) out[b*10 + o] = red[0] + bl[o];
    __syncthreads();
  }
}

// ---------------- launcher ----------------
extern "C" void kernel_launch(void* const* d_in, const int* in_sizes, int n_in,
                              void* d_out, int out_size) {
  const float* x  = (const float*)d_in[0];
  const float* w1 = (const float*)d_in[1];
  const float* b1 = (const float*)d_in[2];
  const float* w2 = (const float*)d_in[3];
  const float* b2 = (const float*)d_in[4];
  const float* w3 = (const float*)d_in[5];
  const float* b3 = (const float*)d_in[6];
  const float* wl = (const float*)d_in[7];
  const float* bl = (const float*)d_in[8];
  float* out = (float*)d_out;

  cudaFuncSetAttribute(fused_kernel, cudaFuncAttributeMaxDynamicSharedMemorySize, SMEM_BYTES);

  init_kernel<<<NSTATE/256, 256>>>(x);
  prep_kernel<<<72, 256>>>(w1, b1, w2, b2, w3, b3);
  for (int step = 0; step < N_STEPS; step++) {
    commit_kernel<<<NSTATE/256, 256>>>();
    for (int s = 0; s < 7; s++)
      fused_kernel<<<dim3(B_IMG, 4, 2), 128, SMEM_BYTES>>>(s);
    err_kernel<<<NSTATE/256, 256>>>();
    update_kernel<<<1, 256>>>();
  }
  commit_kernel<<<NSTATE/256, 256>>>();
  head_kernel<<<B_IMG, 256>>>(wl, bl, out);
}

// round 7
// speedup vs baseline: 1.5333x; 1.0498x over previous
#include <cuda_runtime.h>
#include <math.h>

#define B_IMG   64
#define NPIX    1024
#define NSTATE  (B_IMG*8*NPIX)      // 524288
#define N_STEPS 24

typedef unsigned long long ull;
typedef unsigned int uint;

__device__ __forceinline__ ull pack2(float lo, float hi) {
  ull r; asm("mov.b64 %0, {%1, %2};" : "=l"(r) : "f"(lo), "f"(hi)); return r;
}
__device__ __forceinline__ float2 unpk(ull v) {
  float2 f; asm("mov.b64 {%0, %1}, %2;" : "=f"(f.x), "=f"(f.y) : "l"(v)); return f;
}
#define FMA2(d,a,b) asm("fma.rn.f32x2 %0, %1, %2, %0;" : "+l"(d) : "l"(a), "l"(b))

__device__ __forceinline__ uint f2tf32(float x) {
  uint r; asm("cvt.rna.tf32.f32 %0, %1;" : "=r"(r) : "f"(x)); return r;
}
__device__ __forceinline__ void mma_tf32(float* d, const uint* a, uint b0, uint b1) {
  asm volatile("mma.sync.aligned.m16n8k8.row.col.f32.tf32.tf32.f32 "
    "{%0,%1,%2,%3}, {%4,%5,%6,%7}, {%8,%9}, {%0,%1,%2,%3};"
    : "+f"(d[0]), "+f"(d[1]), "+f"(d[2]), "+f"(d[3])
    : "r"(a[0]), "r"(a[1]), "r"(a[2]), "r"(a[3]), "r"(b0), "r"(b1));
}
__device__ __forceinline__ void cpa16(void* smem_dst, const void* gsrc) {
  unsigned s = (unsigned)__cvta_generic_to_shared(smem_dst);
  asm volatile("cp.async.ca.shared.global [%0], [%1], 16;" :: "r"(s), "l"(gsrc));
}
#define CP_COMMIT() asm volatile("cp.async.commit_group;")
#define CP_WAIT0()  asm volatile("cp.async.wait_group 0;")

// ---------------- device state ----------------
__device__ float g_y[NSTATE];
__device__ float g_y5[NSTATE];
__device__ float g_k[7][NSTATE];
__device__ float g_t, g_dt;
__device__ float g_partial[2048];
__device__ int   g_accept;

// packed weights
__device__ uint2 g_w2t[41472];  // [cc8][tap9][och64][ci9(pad)] = (hi,lo) tf32
__device__ ull g_w1s[256];      // [c8][o2_32]
__device__ ull g_w1t[32], g_b1p[32];
__device__ ull g_w3s[256];      // [ci64][o2_4]
__device__ ull g_w3t[4], g_b3p[4];
__device__ float g_w0f[576];    // conv2 t-channel [och64][tap9]
__device__ float g_b2f[64];

__constant__ float c_toff[7] = {0.f, 0.2f, 0.3f, 0.8f, (float)(8.0/9.0), 1.f, 1.f};
__constant__ float c_coef[7][6] = {
  {0,0,0,0,0,0},
  {0.2f,0,0,0,0,0},
  {(float)(3.0/40.0),(float)(9.0/40.0),0,0,0,0},
  {(float)(44.0/45.0),(float)(-56.0/15.0),(float)(32.0/9.0),0,0,0},
  {(float)(19372.0/6561.0),(float)(-25360.0/2187.0),(float)(64448.0/6561.0),(float)(-212.0/729.0),0,0},
  {(float)(9017.0/3168.0),(float)(-355.0/33.0),(float)(46732.0/5247.0),(float)(49.0/176.0),(float)(-5103.0/18656.0),0},
  {(float)(35.0/384.0),0.f,(float)(500.0/1113.0),(float)(125.0/192.0),(float)(-2187.0/6784.0),(float)(11.0/84.0)}
};
#define B1f ((float)(35.0/384.0))
#define B3f ((float)(500.0/1113.0))
#define B4f ((float)(125.0/192.0))
#define B5f ((float)(-2187.0/6784.0))
#define B6f ((float)(11.0/84.0))
#define E1f ((float)(71.0/57600.0))
#define E3f ((float)(-71.0/16695.0))
#define E4f ((float)(71.0/1920.0))
#define E5f ((float)(-17253.0/339200.0))
#define E6f ((float)(22.0/525.0))
#define E7f ((float)(-1.0/40.0))

// ---------------- init ----------------
__global__ void init_kernel(const float* __restrict__ x) {
  int i = blockIdx.x * 256 + threadIdx.x;
  if (i == 0) { g_t = 0.f; g_dt = 0.1f; g_accept = 0; }
  if (i < NSTATE) {
    int c = i & 7, p = (i >> 3) & 1023, b = i >> 13;
    g_y[i] = (c < 3) ? x[b*3*NPIX + c*NPIX + p] : 0.f;
  }
}

// ---------------- weight prep ----------------
__global__ void prep_kernel(const float* __restrict__ w1, const float* __restrict__ b1,
                            const float* __restrict__ w2, const float* __restrict__ b2,
                            const float* __restrict__ w3, const float* __restrict__ b3) {
  int i = blockIdx.x * 256 + threadIdx.x;
  if (i < 41472) {
    int ci = i % 9;
    int och = (i / 9) % 64;
    int t  = (i / 576) % 9;
    int cc = i / 5184;
    uint2 v = make_uint2(0u, 0u);
    if (ci < 8) {
      float w = w2[och*585 + (cc*8 + ci + 1)*9 + t];
      uint hi = f2tf32(w);
      float hif = __uint_as_float(hi);
      uint lo = f2tf32(w - hif);
      v = make_uint2(hi, lo);
    }
    g_w2t[i] = v;
  }
  if (i < 256) {
    int c = i >> 5, o2 = i & 31;
    g_w1s[i] = pack2(w1[(2*o2)*9 + 1 + c], w1[(2*o2+1)*9 + 1 + c]);
  }
  if (i < 32) {
    g_w1t[i] = pack2(w1[(2*i)*9], w1[(2*i+1)*9]);
    g_b1p[i] = pack2(b1[2*i], b1[2*i+1]);
  }
  if (i < 256) {
    int c = i >> 2, o2 = i & 3;
    g_w3s[i] = pack2(w3[(2*o2)*65 + 1 + c], w3[(2*o2+1)*65 + 1 + c]);
  }
  if (i < 4) {
    g_w3t[i] = pack2(w3[(2*i)*65], w3[(2*i+1)*65]);
    g_b3p[i] = pack2(b3[2*i], b3[2*i+1]);
  }
  if (i < 576) {
    int och = i / 9, t = i % 9;
    g_w0f[i] = w2[och*585 + t];
  }
  if (i < 64) g_b2f[i] = b2[i];
}

// ---------------- fused stage kernel (tf32x3 tensor conv2) ----------------
// grid (64 img, 8 tiles); block 256 thr = 8 warps (2 och-groups x 4 row-groups)
// tile = 4 rows x 32 cols. halo = 6 rows x 34 cols = 204 px.
#define SM_YTS   0        // float yts[204][8]                 6528 B
#define SM_H1    6528     // uint2 h1u[8][204]                13056 B
#define SM_WB    19584    // uint2 wb[2][5184]                82944 B  (h2s overlays wb[0])
#define SM_W1    102528   // ull w1s[256]                      2048 B
#define SM_B1    104576   // ull bias1[32]                      256 B
#define SM_W3    104832   // ull w3s[256]                      2048 B
#define SM_W0    106880   // float w0f[576]                    2304 B
#define SM_B2    109184   // float b2f[64]                      256 B
#define SMEM_BYTES 109440

__global__ __launch_bounds__(256, 2) void fused_kernel(int stage) {
  extern __shared__ char smraw[];
  float* yts  = (float*)(smraw + SM_YTS);
  uint2* h1u  = (uint2*)(smraw + SM_H1);
  uint2* wbu  = (uint2*)(smraw + SM_WB);
  float* h2s  = (float*)(smraw + SM_WB);       // overlay on wb[0] after K loop
  ull*   w1s  = (ull*)  (smraw + SM_W1);
  ull*   bias1= (ull*)  (smraw + SM_B1);
  ull*   w3s  = (ull*)  (smraw + SM_W3);
  float* w0f  = (float*)(smraw + SM_W0);
  float* b2f  = (float*)(smraw + SM_B2);

  int tid  = threadIdx.x;
  int b    = blockIdx.x;
  int tile = blockIdx.y;
  int r0   = tile * 4;

  int warp = tid >> 5, lane = tid & 31;
  int mw  = warp >> 2;        // och group (0..1): och base mw*32
  int nwg = warp & 3;         // row group (0..3): output row r0+nwg
  int g   = lane >> 2;        // groupID
  int cq  = lane & 3;

  float tcur = g_t;
  float dtc  = fminf(g_dt, 1.f - tcur);
  float teval = tcur + c_toff[stage] * dtc;
  ull tev2 = pack2(teval, teval);

  // small weights -> smem
  for (int i = tid; i < 256; i += 256) w1s[i] = g_w1s[i];
  for (int i = tid; i < 256; i += 256) w3s[i] = g_w3s[i];
  for (int i = tid; i < 576; i += 256) w0f[i] = g_w0f[i];
  if (tid < 64) b2f[tid] = g_b2f[tid];
  if (tid < 32) { ull bb = g_b1p[tid]; FMA2(bb, tev2, g_w1t[tid]); bias1[tid] = bb; }

  // prefetch A chunk cc=0 into buffer 0
  for (int i = tid; i < 2592; i += 256) cpa16(wbu + i*2, g_w2t + i*2);
  CP_COMMIT();

  // ---- stage-combined state into yts (haloed 6x34) ----
  for (int p = tid; p < 204; p += 256) {
    int prow = p / 34, pcol = p - prow*34;
    int gr = r0 - 1 + prow, gc = pcol - 1;
    float4 o0 = make_float4(0.f,0.f,0.f,0.f), o1 = o0;
    if (gr >= 0 && gr < 32 && gc >= 0 && gc < 32) {
      int idx = b*1024 + gr*32 + gc;
      const float4* yp = (const float4*)g_y;
      o0 = yp[idx*2]; o1 = yp[idx*2+1];
      for (int j = 0; j < stage; j++) {
        float cf = c_coef[stage][j];
        if (cf != 0.f) {
          float a = dtc * cf;
          const float4* kj = (const float4*)g_k[j];
          float4 k0 = kj[idx*2], k1 = kj[idx*2+1];
          o0.x+=a*k0.x; o0.y+=a*k0.y; o0.z+=a*k0.z; o0.w+=a*k0.w;
          o1.x+=a*k1.x; o1.y+=a*k1.y; o1.z+=a*k1.z; o1.w+=a*k1.w;
        }
      }
    }
    float4* dst = (float4*)(yts + p*8);
    dst[0] = o0; dst[1] = o1;
  }

  // ---- main K loop: 8 ci-chunks x 9 taps, tf32x3 mma ----
  float acc[2][4][4];
  #pragma unroll
  for (int mt = 0; mt < 2; mt++)
    #pragma unroll
    for (int nt = 0; nt < 4; nt++)
      #pragma unroll
      for (int q = 0; q < 4; q++) acc[mt][nt][q] = 0.f;

  int cur = 0;
  #pragma unroll 1
  for (int cc = 0; cc < 8; cc++) {
    __syncthreads();   // prev mma done (h1u reusable); first iter: smem weights ready

    // conv1: produce h1 channels cc*8..+7 (hi/lo tf32) for 204 haloed px
    #pragma unroll 1
    for (int p = tid; p < 204; p += 256) {
      int prow = p / 34, pcol = p - prow*34;
      int gr = r0 - 1 + prow, gc = pcol - 1;
      float o[8];
      if (gr >= 0 && gr < 32 && gc >= 0 && gc < 32) {
        const float4* yv = (const float4*)(yts + p*8);
        float4 a4 = yv[0], b4 = yv[1];
        float yf[8] = {a4.x, a4.y, a4.z, a4.w, b4.x, b4.y, b4.z, b4.w};
        ull yy[8];
        #pragma unroll
        for (int c8 = 0; c8 < 8; c8++) yy[c8] = pack2(yf[c8], yf[c8]);
        #pragma unroll
        for (int q = 0; q < 4; q++) {
          ull aq = bias1[cc*4 + q];
          #pragma unroll
          for (int c8 = 0; c8 < 8; c8++) FMA2(aq, yy[c8], w1s[c8*32 + cc*4 + q]);
          float2 f = unpk(aq);
          o[2*q]   = fmaxf(f.x, 0.f);
          o[2*q+1] = fmaxf(f.y, 0.f);
        }
      } else {
        #pragma unroll
        for (int q = 0; q < 8; q++) o[q] = 0.f;
      }
      #pragma unroll
      for (int ci = 0; ci < 8; ci++) {
        float v = o[ci];
        uint hi = f2tf32(v);
        uint lo = f2tf32(v - __uint_as_float(hi));
        h1u[ci*204 + p] = make_uint2(hi, lo);
      }
    }

    CP_WAIT0();
    __syncthreads();   // h1u ready, wb[cur] ready

    if (cc < 7) {
      const uint2* src = g_w2t + (cc+1)*5184;
      uint2* dst = wbu + (cur^1)*5184;
      for (int i = tid; i < 2592; i += 256) cpa16(dst + i*2, src + i*2);
      CP_COMMIT();
    }

    const uint2* Ab = wbu + cur*5184;
    int kh = 0, kw = 0;
    #pragma unroll 1
    for (int t = 0; t < 9; t++) {
      // A frags (hi/lo) for both m-tiles
      uint ahi[2][4], alo[2][4];
      #pragma unroll
      for (int mt = 0; mt < 2; mt++) {
        const uint2* Am = Ab + (t*64 + mw*32 + mt*16)*9;
        uint2 q00 = Am[(g)*9 + cq];
        uint2 q10 = Am[(g+8)*9 + cq];
        uint2 q01 = Am[(g)*9 + cq + 4];
        uint2 q11 = Am[(g+8)*9 + cq + 4];
        ahi[mt][0]=q00.x; ahi[mt][1]=q10.x; ahi[mt][2]=q01.x; ahi[mt][3]=q11.x;
        alo[mt][0]=q00.y; alo[mt][1]=q10.y; alo[mt][2]=q01.y; alo[mt][3]=q11.y;
      }
      int hbase = (nwg + kh)*34 + kw + g;
      #pragma unroll
      for (int nt = 0; nt < 4; nt++) {
        uint2 p0 = h1u[cq*204       + hbase + nt*8];
        uint2 p1 = h1u[(cq+4)*204   + hbase + nt*8];
        #pragma unroll
        for (int mt = 0; mt < 2; mt++) {
          mma_tf32(acc[mt][nt], ahi[mt], p0.x, p1.x);   // hi*hi
          mma_tf32(acc[mt][nt], ahi[mt], p0.y, p1.y);   // hi*lo
          mma_tf32(acc[mt][nt], alo[mt], p0.x, p1.x);   // lo*hi
        }
      }
      if (++kw == 3) { kw = 0; kh++; }
    }
    cur ^= 1;
  }

  // ---- epilogue: t-channel + bias + relu -> h2s[row4][och64][33] ----
  {
    int gr = r0 + nwg;
    bool r0ok = (gr != 0);    // kh==0 row valid
    bool r2ok = (gr != 31);   // kh==2 row valid
    #pragma unroll
    for (int mt = 0; mt < 2; mt++) {
      #pragma unroll
      for (int rh = 0; rh < 2; rh++) {
        int och = mw*32 + mt*16 + g + rh*8;
        const float* w0 = w0f + och*9;
        float cs0 = w0[3], cs1 = w0[4], cs2 = w0[5];
        if (r0ok) { cs0 += w0[0]; cs1 += w0[1]; cs2 += w0[2]; }
        if (r2ok) { cs0 += w0[6]; cs1 += w0[7]; cs2 += w0[8]; }
        float ball = cs0 + cs1 + cs2;
        float bias = b2f[och];
        float* hrow = h2s + (nwg*64 + och)*33;
        #pragma unroll
        for (int nt = 0; nt < 4; nt++) {
          #pragma unroll
          for (int cb = 0; cb < 2; cb++) {
            int colx = nt*8 + 2*cq + cb;
            float s = ball;
            if (colx == 0)  s -= cs0;
            if (colx == 31) s -= cs2;
            float v = acc[mt][nt][rh*2 + cb] + teval*s + bias;
            hrow[colx] = fmaxf(v, 0.f);
          }
        }
      }
    }
  }
  __syncthreads();

  // ---- conv3 (65->8 1x1): 2 threads/px, 4 och each ----
  {
    int px   = tid >> 1;        // 0..127
    int half = tid & 1;
    int row = px >> 5, col = px & 31;
    int o2a = half*2, o2b = half*2 + 1;
    ull k0 = g_b3p[o2a]; FMA2(k0, tev2, g_w3t[o2a]);
    ull k1 = g_b3p[o2b]; FMA2(k1, tev2, g_w3t[o2b]);
    const float* hcol = h2s + (row*64)*33 + col;
    #pragma unroll 8
    for (int c = 0; c < 64; c++) {
      float h = hcol[c*33];
      ull hh = pack2(h, h);
      FMA2(k0, hh, w3s[c*4 + o2a]);
      FMA2(k1, hh, w3s[c*4 + o2b]);
    }
    float2 f0 = unpk(k0), f1 = unpk(k1);
    int idx = b*1024 + (r0 + row)*32 + col;
    ((float4*)g_k[stage])[idx*2 + half] = make_float4(f0.x, f0.y, f1.x, f1.y);
  }
}

// ---------------- y5 + error partials ----------------
__global__ __launch_bounds__(256) void err_kernel() {
  __shared__ float red[256];
  int tid = threadIdx.x;
  int e = blockIdx.x * 256 + tid;
  float dtc = fminf(g_dt, 1.f - g_t);
  float k0 = g_k[0][e], k2 = g_k[2][e], k3 = g_k[3][e];
  float k4 = g_k[4][e], k5 = g_k[5][e], k6 = g_k[6][e];
  float yv = g_y[e];
  float y5 = yv + dtc*(B1f*k0 + B3f*k2 + B4f*k3 + B5f*k4 + B6f*k5);
  g_y5[e] = y5;
  float err = dtc*(E1f*k0 + E3f*k2 + E4f*k3 + E5f*k4 + E6f*k5 + E7f*k6);
  float tol = 1e-3f + 1e-3f * fmaxf(fabsf(yv), fabsf(y5));
  float r = err / tol;
  red[tid] = r * r;
  __syncthreads();
  for (int s = 128; s > 0; s >>= 1) { if (tid < s) red[tid] += red[tid+s]; __syncthreads(); }
  if (tid == 0) g_partial[blockIdx.x] = red[0];
}

// ---------------- step controller ----------------
__global__ void update_kernel() {
  __shared__ float red[256];
  int tid = threadIdx.x;
  float s0 = 0.f;
  for (int i = tid; i < 2048; i += 256) s0 += g_partial[i];
  red[tid] = s0;
  __syncthreads();
  for (int s = 128; s > 0; s >>= 1) { if (tid < s) red[tid] += red[tid+s]; __syncthreads(); }
  if (tid == 0) {
    float err_norm = sqrtf(red[0] * (1.f / (float)NSTATE));
    float tcur = g_t, dt = g_dt;
    float dtc  = fminf(dt, 1.f - tcur);
    bool done = tcur >= 1.f - 1e-7f;
    bool adv  = (err_norm <= 1.f) && (!done);
    g_accept = adv ? 1 : 0;
    g_t = adv ? (tcur + dtc) : tcur;
    float safe = fmaxf(err_norm, 1e-10f);
    float factor = 0.9f * powf(safe, -0.2f);
    factor = fminf(fmaxf(factor, 0.2f), 10.f);
    g_dt = done ? dt : dtc * factor;
  }
}

__global__ void commit_kernel() {
  if (g_accept == 0) return;
  int i = blockIdx.x * 256 + threadIdx.x;
  g_y[i] = g_y5[i];
}

// ---------------- final linear head ----------------
__global__ __launch_bounds__(256) void head_kernel(const float* __restrict__ wl,
                                                   const float* __restrict__ bl,
                                                   float* __restrict__ out) {
  __shared__ float ys[8192];
  __shared__ float red[256];
  int b = blockIdx.x, tid = threadIdx.x;
  const float* yb = g_y + (size_t)b * 8192;
  for (int i = tid; i < 8192; i += 256) {
    int px = i >> 3, c = i & 7;
    ys[c*1024 + px] = yb[i];
  }
  __syncthreads();
  for (int o = 0; o < 10; o++) {
    float s = 0.f;
    const float* wo = wl + (size_t)o * 8192;
    for (int i = tid; i < 8192; i += 256) s += wo[i] * ys[i];
    red[tid] = s; __syncthreads();
    for (int st = 128; st > 0; st >>= 1) { if (tid < st) red[tid] += red[tid+st]; __syncthreads(); }
    if (tid == 0) out[b*10 + o] = red[0] + bl[o];
    __syncthreads();
  }
}

// ---------------- launcher ----------------
extern "C" void kernel_launch(void* const* d_in, const int* in_sizes, int n_in,
                              void* d_out, int out_size) {
  const float* x  = (const float*)d_in[0];
  const float* w1 = (const float*)d_in[1];
  const float* b1 = (const float*)d_in[2];
  const float* w2 = (const float*)d_in[3];
  const float* b2 = (const float*)d_in[4];
  const float* w3 = (const float*)d_in[5];
  const float* b3 = (const float*)d_in[6];
  const float* wl = (const float*)d_in[7];
  const float* bl = (const float*)d_in[8];
  float* out = (float*)d_out;

  cudaFuncSetAttribute(fused_kernel, cudaFuncAttributeMaxDynamicSharedMemorySize, SMEM_BYTES);

  init_kernel<<<NSTATE/256, 256>>>(x);
  prep_kernel<<<162, 256>>>(w1, b1, w2, b2, w3, b3);
  for (int step = 0; step < N_STEPS; step++) {
    commit_kernel<<<NSTATE/256, 256>>>();
    for (int s = 0; s < 7; s++)
      fused_kernel<<<dim3(B_IMG, 8), 256, SMEM_BYTES>>>(s);
    err_kernel<<<NSTATE/256, 256>>>();
    update_kernel<<<1, 256>>>();
  }
  commit_kernel<<<NSTATE/256, 256>>>();
  head_kernel<<<B_IMG, 256>>>(wl, bl, out);
}